// round 11
// baseline (speedup 1.0000x reference)
#include <cuda_runtime.h>

#define N 768
#define E_N 24576
#define CAP 128

// -------- device scratch (zero-initialized at module load; self-resetting) --------
static __device__ int   g_winner[N * N];             // 0 = empty, else winning e+1
static __device__ int   g_cnt[N];
static __device__ int   g_list[N * CAP];
static __device__ float g_evals[E_N * 64];           // edge MLP out [E,8,8]
static __device__ float g_mtr1[N * N * 8];           // walk result
static __device__ float g_mtrT[N * N * 8];           // mtr transposed: [j][i][c]
static __device__ int   g_idx64;

typedef unsigned long long u64;

// -------- f32x2 helpers --------
__device__ __forceinline__ u64 pk2(float lo, float hi) {
    u64 r;
    asm("mov.b64 %0, {%1, %2};" : "=l"(r) : "r"(__float_as_uint(lo)), "r"(__float_as_uint(hi)));
    return r;
}
__device__ __forceinline__ void upk2(u64 p, float& lo, float& hi) {
    unsigned a, b;
    asm("mov.b64 {%0, %1}, %2;" : "=r"(a), "=r"(b) : "l"(p));
    lo = __uint_as_float(a); hi = __uint_as_float(b);
}
__device__ __forceinline__ u64 fma2(u64 a, u64 b, u64 c) {
    u64 d;
    asm("fma.rn.f32x2 %0, %1, %2, %3;" : "=l"(d) : "l"(a), "l"(b), "l"(c));
    return d;
}
__device__ __forceinline__ u64 mul2(u64 a, u64 b) {
    u64 d;
    asm("mul.rn.f32x2 %0, %1, %2;" : "=l"(d) : "l"(a), "l"(b));
    return d;
}
__device__ __forceinline__ u64 relu2(u64 p) {
    float lo, hi; upk2(p, lo, hi);
    return pk2(fmaxf(lo, 0.f), fmaxf(hi, 0.f));
}

__device__ __forceinline__ int load_idx(const void* ei, int pos, int use64) {
    if (use64) return (int)((const long long*)ei)[pos];
    return ((const int*)ei)[pos];
}

// -------- prep: dtype detect (block 576) + tiled transpose (blocks 0..575) --------
__global__ void k_prep(const int* __restrict__ ei32, const float* __restrict__ mtr) {
    if (blockIdx.x == 576) {
        __shared__ int any;
        if (threadIdx.x == 0) any = 0;
        __syncthreads();
        for (int j = threadIdx.x * 2 + 1; j < 4096; j += 512)
            if (ei32[j] != 0) any = 1;
        __syncthreads();
        if (threadIdx.x == 0) g_idx64 = (any == 0) ? 1 : 0;
        return;
    }
    // 32x32 element tile (element = 8 floats = 32B); pitch 264 floats kills LDS conflicts
    __shared__ __align__(16) float sm[32 * 264];
    int t = blockIdx.x;
    int I0 = (t / 24) * 32, J0 = (t % 24) * 32;
    int tid = threadIdx.x;
    #pragma unroll
    for (int q = 0; q < 4; q++) {
        int idx = q * 256 + tid;
        int il = idx >> 5, jl = idx & 31;
        const float4* p = (const float4*)&mtr[((I0 + il) * N + (J0 + jl)) * 8];
        float4 v0 = p[0], v1 = p[1];
        float* s = &sm[jl * 264 + il * 8];     // store transposed
        *(float4*)s = v0; *(float4*)(s + 4) = v1;
    }
    __syncthreads();
    #pragma unroll
    for (int q = 0; q < 4; q++) {
        int idx = q * 256 + tid;
        int jl = idx >> 5, il = idx & 31;
        const float* s = &sm[jl * 264 + il * 8];
        float4 v0 = *(const float4*)s, v1 = *(const float4*)(s + 4);
        float4* qp = (float4*)&g_mtrT[((J0 + jl) * N + (I0 + il)) * 8];  // coalesced
        qp[0] = v0; qp[1] = v1;
    }
}

// -------- last-write-wins: store e+1 into zeroed cells --------
__global__ void k_winner(const void* __restrict__ ei) {
    int e = blockIdx.x * 256 + threadIdx.x;
    int use64 = g_idx64;
    int s = load_idx(ei, e, use64);
    int d = load_idx(ei, E_N + e, use64);
    atomicMax(&g_winner[s * N + d], e + 1);
}

// -------- edge MLP (blocks 0..95) + winner-build & cell reset (blocks 96..191) --------
__global__ void k_edge(const void* __restrict__ ei, const float* __restrict__ ea,
                       const float* __restrict__ feat,
                       const float* __restrict__ w0, const float* __restrict__ b0,
                       const float* __restrict__ w1, const float* __restrict__ b1,
                       const float* __restrict__ w2, const float* __restrict__ b2,
                       const float* __restrict__ w3, const float* __restrict__ b3) {
    if (blockIdx.x >= 96) {
        int e = (blockIdx.x - 96) * 256 + threadIdx.x;
        int use64 = g_idx64;
        int s = load_idx(ei, e, use64);
        int d = load_idx(ei, E_N + e, use64);
        int cell = s * N + d;
        if (g_winner[cell] == e + 1) {
            int slot = atomicAdd(&g_cnt[d], 1);
            if (slot < CAP) g_list[d * CAP + slot] = e;
            g_winner[cell] = 0;                // self-reset for next replay
        }
        return;
    }
    // transposed weights: wT[i*OUT + o]  (broadcast reads, 16B-aligned float4 rows)
    __shared__ __align__(16) float wT0[20 * 32], wT1[32 * 32], wT2[32 * 32], wT3[32 * 64];
    __shared__ float sb0[32], sb1[32], sb2[32], sb3[64];
    int tid = threadIdx.x;
    for (int t = tid; t < 640; t += 256)  { int o = t / 20, i = t % 20; wT0[i * 32 + o] = w0[t]; }
    for (int t = tid; t < 1024; t += 256) { int o = t >> 5, i = t & 31; wT1[i * 32 + o] = w1[t]; wT2[i * 32 + o] = w2[t]; }
    for (int t = tid; t < 2048; t += 256) { int o = t >> 5, i = t & 31; wT3[i * 64 + o] = w3[t]; }
    if (tid < 32) { sb0[tid] = b0[tid]; sb1[tid] = b1[tid]; sb2[tid] = b2[tid]; }
    if (tid < 64) sb3[tid] = b3[tid];
    __syncthreads();

    int e = blockIdx.x * 256 + tid;
    int use64 = g_idx64;
    int s = load_idx(ei, e, use64);
    int d = load_idx(ei, E_N + e, use64);

    float x[20];
    {
        float4 v = *(const float4*)&ea[e * 4];
        x[0] = v.x; x[1] = v.y; x[2] = v.z; x[3] = v.w;
        v = *(const float4*)&feat[s * 8];     x[4] = v.x;  x[5] = v.y;  x[6] = v.z;  x[7] = v.w;
        v = *(const float4*)&feat[s * 8 + 4]; x[8] = v.x;  x[9] = v.y;  x[10] = v.z; x[11] = v.w;
        v = *(const float4*)&feat[d * 8];     x[12] = v.x; x[13] = v.y; x[14] = v.z; x[15] = v.w;
        v = *(const float4*)&feat[d * 8 + 4]; x[16] = v.x; x[17] = v.y; x[18] = v.z; x[19] = v.w;
    }

    float h[32], h2[32];
    // layer 0: 20 -> 32
    #pragma unroll
    for (int o = 0; o < 32; o++) h[o] = sb0[o];
    #pragma unroll
    for (int i = 0; i < 20; i++) {
        float xi = x[i];
        #pragma unroll
        for (int o = 0; o < 32; o += 4) {
            float4 w = *(const float4*)&wT0[i * 32 + o];
            h[o] += xi * w.x; h[o+1] += xi * w.y; h[o+2] += xi * w.z; h[o+3] += xi * w.w;
        }
    }
    #pragma unroll
    for (int o = 0; o < 32; o++) h[o] = fmaxf(h[o], 0.f);

    // layer 1: 32 -> 32
    #pragma unroll
    for (int o = 0; o < 32; o++) h2[o] = sb1[o];
    #pragma unroll
    for (int i = 0; i < 32; i++) {
        float xi = h[i];
        #pragma unroll
        for (int o = 0; o < 32; o += 4) {
            float4 w = *(const float4*)&wT1[i * 32 + o];
            h2[o] += xi * w.x; h2[o+1] += xi * w.y; h2[o+2] += xi * w.z; h2[o+3] += xi * w.w;
        }
    }
    #pragma unroll
    for (int o = 0; o < 32; o++) h2[o] = fmaxf(h2[o], 0.f);

    // layer 2: 32 -> 32
    #pragma unroll
    for (int o = 0; o < 32; o++) h[o] = sb2[o];
    #pragma unroll
    for (int i = 0; i < 32; i++) {
        float xi = h2[i];
        #pragma unroll
        for (int o = 0; o < 32; o += 4) {
            float4 w = *(const float4*)&wT2[i * 32 + o];
            h[o] += xi * w.x; h[o+1] += xi * w.y; h[o+2] += xi * w.z; h[o+3] += xi * w.w;
        }
    }
    #pragma unroll
    for (int o = 0; o < 32; o++) h[o] = fmaxf(h[o], 0.f);

    // layer 3: 32 -> 64 (no relu)
    float o64[64];
    #pragma unroll
    for (int o = 0; o < 64; o++) o64[o] = sb3[o];
    #pragma unroll
    for (int i = 0; i < 32; i++) {
        float xi = h[i];
        #pragma unroll
        for (int o = 0; o < 64; o += 4) {
            float4 w = *(const float4*)&wT3[i * 64 + o];
            o64[o] += xi * w.x; o64[o+1] += xi * w.y; o64[o+2] += xi * w.z; o64[o+3] += xi * w.w;
        }
    }
    #pragma unroll
    for (int c = 0; c < 64; c += 4) {
        float4 v; v.x = o64[c]; v.y = o64[c+1]; v.z = o64[c+2]; v.w = o64[c+3];
        *(float4*)&g_evals[e * 64 + c] = v;
    }
}

// -------- walk contraction: coalesced via g_mtrT, f32x2 packed over t --------
__global__ void k_walk(const void* __restrict__ ei) {
    int k = blockIdx.x;
    int tid = threadIdx.x;
    __shared__ __align__(16) float sM[8 * 64];
    __shared__ int ssrc[8];
    int cnt = min(g_cnt[k], CAP);
    int use64 = g_idx64;

    u64 acc[3][4];
    #pragma unroll
    for (int r = 0; r < 3; r++)
        #pragma unroll
        for (int t = 0; t < 4; t++) acc[r][t] = 0ULL;

    for (int base = 0; base < cnt; base += 8) {
        int nc = min(8, cnt - base);
        __syncthreads();
        for (int t = tid; t < nc * 64; t += 256) {
            int e = g_list[k * CAP + base + (t >> 6)];
            sM[t] = g_evals[e * 64 + (t & 63)];
        }
        if (tid < nc) ssrc[tid] = load_idx(ei, g_list[k * CAP + base + tid], use64);
        __syncthreads();

        for (int c = 0; c < nc; c++) {
            int s = ssrc[c];
            float av[3][8];
            #pragma unroll
            for (int r = 0; r < 3; r++) {
                int i = tid + (r << 8);
                const float4* p = (const float4*)&g_mtrT[(s * N + i) * 8];  // coalesced
                float4 v0 = p[0], v1 = p[1];
                av[r][0] = v0.x; av[r][1] = v0.y; av[r][2] = v0.z; av[r][3] = v0.w;
                av[r][4] = v1.x; av[r][5] = v1.y; av[r][6] = v1.z; av[r][7] = v1.w;
            }
            #pragma unroll
            for (int cc = 0; cc < 8; cc++) {
                const ulonglong2* mp = (const ulonglong2*)&sM[c * 64 + cc * 8];
                ulonglong2 ma = mp[0], mb = mp[1];
                #pragma unroll
                for (int r = 0; r < 3; r++) {
                    u64 dv = pk2(av[r][cc], av[r][cc]);
                    acc[r][0] = fma2(dv, ma.x, acc[r][0]);
                    acc[r][1] = fma2(dv, ma.y, acc[r][1]);
                    acc[r][2] = fma2(dv, mb.x, acc[r][2]);
                    acc[r][3] = fma2(dv, mb.y, acc[r][3]);
                }
            }
        }
    }
    u64 eighth = pk2(0.125f, 0.125f);
    #pragma unroll
    for (int r = 0; r < 3; r++) {
        int i = tid + (r << 8);
        float4 o0, o1;
        upk2(mul2(acc[r][0], eighth), o0.x, o0.y);
        upk2(mul2(acc[r][1], eighth), o0.z, o0.w);
        upk2(mul2(acc[r][2], eighth), o1.x, o1.y);
        upk2(mul2(acc[r][3], eighth), o1.z, o1.w);
        *(float4*)&g_mtr1[(i * N + k) * 8]     = o0;
        *(float4*)&g_mtr1[(i * N + k) * 8 + 4] = o1;
    }
    if (tid == 0) g_cnt[k] = 0;               // self-reset for next replay
}

// -------- output MLP: 2 rows/thread, f32x2, staged layer-0 to cap registers --------
__global__ void __launch_bounds__(128) k_out(
        const float* __restrict__ mtr, const float* __restrict__ feat,
        float* __restrict__ out,
        const float* __restrict__ w0, const float* __restrict__ b0,
        const float* __restrict__ w1, const float* __restrict__ b1,
        const float* __restrict__ w2, const float* __restrict__ b2,
        const float* __restrict__ w3, const float* __restrict__ b3) {
    // duplicated weight packs, transposed: wd[j*OUT + o] = (w[o][j], w[o][j])
    __shared__ __align__(16) u64 wd0[33 * 32], wd1[32 * 32], wd2[32 * 32], wd3[32 * 8];
    __shared__ __align__(16) u64 bd0[32], bd1[32], bd2[32], bd3[8];
    int tid = threadIdx.x;
    for (int t = tid; t < 1056; t += 128) { int j = t >> 5, o = t & 31; float w = w0[o * 33 + j]; wd0[t] = pk2(w, w); }
    for (int t = tid; t < 1024; t += 128) {
        int j = t >> 5, o = t & 31;
        float wa = w1[o * 32 + j]; wd1[t] = pk2(wa, wa);
        float wb = w2[o * 32 + j]; wd2[t] = pk2(wb, wb);
    }
    for (int t = tid; t < 256; t += 128) { int j = t >> 3, o = t & 7; float w = w3[o * 32 + j]; wd3[t] = pk2(w, w); }
    if (tid < 32) {
        float v;
        v = b0[tid]; bd0[tid] = pk2(v, v);
        v = b1[tid]; bd1[tid] = pk2(v, v);
        v = b2[tid]; bd2[tid] = pk2(v, v);
        if (tid < 8) { v = b3[tid]; bd3[tid] = pk2(v, v); }
    }
    __syncthreads();

    int i  = blockIdx.y;
    int k1 = blockIdx.x * 256 + tid;
    int k2 = k1 + 128;
    int base1 = (i * N + k1) * 8, base2 = (i * N + k2) * 8;
    int bT1 = (k1 * N + i) * 8, bT2 = (k2 * N + i) * 8;

    u64 acc[32], h[32];
    u64 xp[17];

    // ---- stage A: mtr1 inputs (j = 0..15) ----
    {
        float4 a0 = *(const float4*)&g_mtr1[base1], a1 = *(const float4*)&g_mtr1[base1 + 4];
        float4 c0 = *(const float4*)&g_mtr1[base2], c1 = *(const float4*)&g_mtr1[base2 + 4];
        xp[0] = pk2(a0.x, c0.x); xp[1] = pk2(a0.y, c0.y); xp[2] = pk2(a0.z, c0.z); xp[3] = pk2(a0.w, c0.w);
        xp[4] = pk2(a1.x, c1.x); xp[5] = pk2(a1.y, c1.y); xp[6] = pk2(a1.z, c1.z); xp[7] = pk2(a1.w, c1.w);
        a0 = *(const float4*)&g_mtr1[bT1]; a1 = *(const float4*)&g_mtr1[bT1 + 4];
        c0 = *(const float4*)&g_mtr1[bT2]; c1 = *(const float4*)&g_mtr1[bT2 + 4];
        xp[8]  = pk2(a0.x, c0.x); xp[9]  = pk2(a0.y, c0.y); xp[10] = pk2(a0.z, c0.z); xp[11] = pk2(a0.w, c0.w);
        xp[12] = pk2(a1.x, c1.x); xp[13] = pk2(a1.y, c1.y); xp[14] = pk2(a1.z, c1.z); xp[15] = pk2(a1.w, c1.w);
    }
    {
        const ulonglong2* B = (const ulonglong2*)bd0;
        #pragma unroll
        for (int oo = 0; oo < 16; oo++) { ulonglong2 b = B[oo]; acc[2*oo] = b.x; acc[2*oo+1] = b.y; }
        const ulonglong2* W = (const ulonglong2*)wd0;
        #pragma unroll
        for (int j = 0; j < 16; j++) {
            u64 xj = xp[j];
            #pragma unroll
            for (int oo = 0; oo < 16; oo++) {
                ulonglong2 w = W[j * 16 + oo];
                acc[2*oo]   = fma2(xj, w.x, acc[2*oo]);
                acc[2*oo+1] = fma2(xj, w.y, acc[2*oo+1]);
            }
        }
    }
    // ---- stage B: feat + eye inputs (j = 16..32) ----
    {
        float4 a0 = *(const float4*)&feat[k1 * 8], a1 = *(const float4*)&feat[k1 * 8 + 4];
        float4 c0 = *(const float4*)&feat[k2 * 8], c1 = *(const float4*)&feat[k2 * 8 + 4];
        xp[0] = pk2(a0.x, c0.x); xp[1] = pk2(a0.y, c0.y); xp[2] = pk2(a0.z, c0.z); xp[3] = pk2(a0.w, c0.w);
        xp[4] = pk2(a1.x, c1.x); xp[5] = pk2(a1.y, c1.y); xp[6] = pk2(a1.z, c1.z); xp[7] = pk2(a1.w, c1.w);
        a0 = *(const float4*)&feat[i * 8]; a1 = *(const float4*)&feat[i * 8 + 4];
        xp[8]  = pk2(a0.x, a0.x); xp[9]  = pk2(a0.y, a0.y); xp[10] = pk2(a0.z, a0.z); xp[11] = pk2(a0.w, a0.w);
        xp[12] = pk2(a1.x, a1.x); xp[13] = pk2(a1.y, a1.y); xp[14] = pk2(a1.z, a1.z); xp[15] = pk2(a1.w, a1.w);
        xp[16] = pk2(i == k1 ? 1.f : 0.f, i == k2 ? 1.f : 0.f);
    }
    {
        const ulonglong2* W = (const ulonglong2*)wd0;
        #pragma unroll
        for (int j = 0; j < 17; j++) {
            u64 xj = xp[j];
            #pragma unroll
            for (int oo = 0; oo < 16; oo++) {
                ulonglong2 w = W[(16 + j) * 16 + oo];
                acc[2*oo]   = fma2(xj, w.x, acc[2*oo]);
                acc[2*oo+1] = fma2(xj, w.y, acc[2*oo+1]);
            }
        }
        #pragma unroll
        for (int o = 0; o < 32; o++) h[o] = relu2(acc[o]);
    }
    // layer 1: 32 -> 32
    {
        const ulonglong2* B = (const ulonglong2*)bd1;
        #pragma unroll
        for (int oo = 0; oo < 16; oo++) { ulonglong2 b = B[oo]; acc[2*oo] = b.x; acc[2*oo+1] = b.y; }
        const ulonglong2* W = (const ulonglong2*)wd1;
        #pragma unroll
        for (int j = 0; j < 32; j++) {
            u64 xj = h[j];
            #pragma unroll
            for (int oo = 0; oo < 16; oo++) {
                ulonglong2 w = W[j * 16 + oo];
                acc[2*oo]   = fma2(xj, w.x, acc[2*oo]);
                acc[2*oo+1] = fma2(xj, w.y, acc[2*oo+1]);
            }
        }
        #pragma unroll
        for (int o = 0; o < 32; o++) acc[o] = relu2(acc[o]);
    }
    // layer 2: 32 -> 32
    {
        const ulonglong2* B = (const ulonglong2*)bd2;
        #pragma unroll
        for (int oo = 0; oo < 16; oo++) { ulonglong2 b = B[oo]; h[2*oo] = b.x; h[2*oo+1] = b.y; }
        const ulonglong2* W = (const ulonglong2*)wd2;
        #pragma unroll
        for (int j = 0; j < 32; j++) {
            u64 xj = acc[j];
            #pragma unroll
            for (int oo = 0; oo < 16; oo++) {
                ulonglong2 w = W[j * 16 + oo];
                h[2*oo]   = fma2(xj, w.x, h[2*oo]);
                h[2*oo+1] = fma2(xj, w.y, h[2*oo+1]);
            }
        }
        #pragma unroll
        for (int o = 0; o < 32; o++) h[o] = relu2(h[o]);
    }
    // layer 3: 32 -> 8
    u64 y[8];
    {
        const ulonglong2* B = (const ulonglong2*)bd3;
        #pragma unroll
        for (int oo = 0; oo < 4; oo++) { ulonglong2 b = B[oo]; y[2*oo] = b.x; y[2*oo+1] = b.y; }
        const ulonglong2* W = (const ulonglong2*)wd3;
        #pragma unroll
        for (int j = 0; j < 32; j++) {
            u64 xj = h[j];
            #pragma unroll
            for (int oo = 0; oo < 4; oo++) {
                ulonglong2 w = W[j * 4 + oo];
                y[2*oo]   = fma2(xj, w.x, y[2*oo]);
                y[2*oo+1] = fma2(xj, w.y, y[2*oo+1]);
            }
        }
    }
    // residual add + store both rows
    {
        float yr1[8], yr2[8];
        #pragma unroll
        for (int c = 0; c < 8; c++) upk2(y[c], yr1[c], yr2[c]);
        float4 m0 = *(const float4*)&mtr[base1], m1 = *(const float4*)&mtr[base1 + 4];
        float4 o0, o1;
        o0.x = m0.x + yr1[0]; o0.y = m0.y + yr1[1]; o0.z = m0.z + yr1[2]; o0.w = m0.w + yr1[3];
        o1.x = m1.x + yr1[4]; o1.y = m1.y + yr1[5]; o1.z = m1.z + yr1[6]; o1.w = m1.w + yr1[7];
        *(float4*)&out[base1] = o0; *(float4*)&out[base1 + 4] = o1;
        m0 = *(const float4*)&mtr[base2]; m1 = *(const float4*)&mtr[base2 + 4];
        o0.x = m0.x + yr2[0]; o0.y = m0.y + yr2[1]; o0.z = m0.z + yr2[2]; o0.w = m0.w + yr2[3];
        o1.x = m1.x + yr2[4]; o1.y = m1.y + yr2[5]; o1.z = m1.z + yr2[6]; o1.w = m1.w + yr2[7];
        *(float4*)&out[base2] = o0; *(float4*)&out[base2 + 4] = o1;
    }
}

extern "C" void kernel_launch(void* const* d_in, const int* in_sizes, int n_in,
                              void* d_out, int out_size) {
    const float* mtr  = (const float*)d_in[0];
    const float* feat = (const float*)d_in[1];
    const void*  ei   = d_in[2];
    const float* ea   = (const float*)d_in[3];
    const float* ew0 = (const float*)d_in[4],  *eb0 = (const float*)d_in[5];
    const float* ew1 = (const float*)d_in[6],  *eb1 = (const float*)d_in[7];
    const float* ew2 = (const float*)d_in[8],  *eb2 = (const float*)d_in[9];
    const float* ew3 = (const float*)d_in[10], *eb3 = (const float*)d_in[11];
    const float* ow0 = (const float*)d_in[12], *ob0 = (const float*)d_in[13];
    const float* ow1 = (const float*)d_in[14], *ob1 = (const float*)d_in[15];
    const float* ow2 = (const float*)d_in[16], *ob2 = (const float*)d_in[17];
    const float* ow3 = (const float*)d_in[18], *ob3 = (const float*)d_in[19];
    float* out = (float*)d_out;

    k_prep<<<577, 256>>>((const int*)ei, mtr);
    k_winner<<<E_N / 256, 256>>>(ei);
    k_edge<<<192, 256>>>(ei, ea, feat, ew0, eb0, ew1, eb1, ew2, eb2, ew3, eb3);
    k_walk<<<N, 256>>>(ei);
    dim3 g(3, N);
    k_out<<<g, 128>>>(mtr, feat, out, ow0, ob0, ow1, ob1, ow2, ob2, ow3, ob3);
}

// round 14
// speedup vs baseline: 1.0513x; 1.0513x over previous
#include <cuda_runtime.h>

#define N 768
#define E_N 24576
#define CAP 128

// -------- device scratch (zero-initialized at module load; self-resetting) --------
static __device__ int   g_winner[N * N];             // 0 = empty, else winning e+1
static __device__ int   g_cnt[N];
static __device__ int   g_list[N * CAP];
static __device__ float g_evals[E_N * 64];           // edge MLP out [E,8,8]
static __device__ float g_mtr1[N * N * 8];           // walk result
static __device__ float g_mtrT[N * N * 8];           // mtr transposed: [j][i][c]
static __device__ int   g_idx64;

typedef unsigned long long u64;

// -------- f32x2 helpers --------
__device__ __forceinline__ u64 pk2(float lo, float hi) {
    u64 r;
    asm("mov.b64 %0, {%1, %2};" : "=l"(r) : "r"(__float_as_uint(lo)), "r"(__float_as_uint(hi)));
    return r;
}
__device__ __forceinline__ void upk2(u64 p, float& lo, float& hi) {
    unsigned a, b;
    asm("mov.b64 {%0, %1}, %2;" : "=r"(a), "=r"(b) : "l"(p));
    lo = __uint_as_float(a); hi = __uint_as_float(b);
}
__device__ __forceinline__ u64 fma2(u64 a, u64 b, u64 c) {
    u64 d;
    asm("fma.rn.f32x2 %0, %1, %2, %3;" : "=l"(d) : "l"(a), "l"(b), "l"(c));
    return d;
}
__device__ __forceinline__ u64 mul2(u64 a, u64 b) {
    u64 d;
    asm("mul.rn.f32x2 %0, %1, %2;" : "=l"(d) : "l"(a), "l"(b));
    return d;
}
__device__ __forceinline__ u64 relu2(u64 p) {
    float lo, hi; upk2(p, lo, hi);
    return pk2(fmaxf(lo, 0.f), fmaxf(hi, 0.f));
}

__device__ __forceinline__ int load_idx(const void* ei, int pos, int use64) {
    if (use64) return (int)((const long long*)ei)[pos];
    return ((const int*)ei)[pos];
}

// -------- k_pre: winner (blocks 0..95, block-local dtype vote) +
//          tiled transpose (96..671) + global dtype detect (672) --------
__global__ void k_pre(const int* __restrict__ ei32, const float* __restrict__ mtr,
                      const void* __restrict__ ei) {
    int b = blockIdx.x;
    int tid = threadIdx.x;
    if (b < 96) {
        // last-write-wins winner; dtype decided by block-local vote over this
        // block's 256 odd words (int64 => all high-halves zero)
        int e = b * 256 + tid;
        int any = __syncthreads_or(ei32[2 * e + 1] != 0);
        int use64 = (any == 0) ? 1 : 0;
        int s = load_idx(ei, e, use64);
        int d = load_idx(ei, E_N + e, use64);
        atomicMax(&g_winner[s * N + d], e + 1);
        return;
    }
    if (b == 672) {
        __shared__ int any;
        if (tid == 0) any = 0;
        __syncthreads();
        for (int j = tid * 2 + 1; j < 4096; j += 512)
            if (ei32[j] != 0) any = 1;
        __syncthreads();
        if (tid == 0) g_idx64 = (any == 0) ? 1 : 0;
        return;
    }
    // 32x32 element tile (element = 8 floats = 32B); pitch 264 floats kills LDS conflicts
    __shared__ __align__(16) float sm[32 * 264];
    int t = b - 96;
    int I0 = (t / 24) * 32, J0 = (t % 24) * 32;
    #pragma unroll
    for (int q = 0; q < 4; q++) {
        int idx = q * 256 + tid;
        int il = idx >> 5, jl = idx & 31;
        const float4* p = (const float4*)&mtr[((I0 + il) * N + (J0 + jl)) * 8];
        float4 v0 = p[0], v1 = p[1];
        float* s = &sm[jl * 264 + il * 8];     // store transposed
        *(float4*)s = v0; *(float4*)(s + 4) = v1;
    }
    __syncthreads();
    #pragma unroll
    for (int q = 0; q < 4; q++) {
        int idx = q * 256 + tid;
        int jl = idx >> 5, il = idx & 31;
        const float* s = &sm[jl * 264 + il * 8];
        float4 v0 = *(const float4*)s, v1 = *(const float4*)(s + 4);
        float4* qp = (float4*)&g_mtrT[((J0 + jl) * N + (I0 + il)) * 8];  // coalesced
        qp[0] = v0; qp[1] = v1;
    }
}

// -------- edge MLP (blocks 0..95) + winner-build & cell reset (blocks 96..191) --------
__global__ void k_edge(const void* __restrict__ ei, const float* __restrict__ ea,
                       const float* __restrict__ feat,
                       const float* __restrict__ w0, const float* __restrict__ b0,
                       const float* __restrict__ w1, const float* __restrict__ b1,
                       const float* __restrict__ w2, const float* __restrict__ b2,
                       const float* __restrict__ w3, const float* __restrict__ b3) {
    if (blockIdx.x >= 96) {
        int e = (blockIdx.x - 96) * 256 + threadIdx.x;
        int use64 = g_idx64;
        int s = load_idx(ei, e, use64);
        int d = load_idx(ei, E_N + e, use64);
        int cell = s * N + d;
        if (g_winner[cell] == e + 1) {
            int slot = atomicAdd(&g_cnt[d], 1);
            if (slot < CAP) g_list[d * CAP + slot] = e;
            g_winner[cell] = 0;                // self-reset for next replay
        }
        return;
    }
    // transposed weights: wT[i*OUT + o]  (broadcast reads, 16B-aligned float4 rows)
    __shared__ __align__(16) float wT0[20 * 32], wT1[32 * 32], wT2[32 * 32], wT3[32 * 64];
    __shared__ float sb0[32], sb1[32], sb2[32], sb3[64];
    int tid = threadIdx.x;
    for (int t = tid; t < 640; t += 256)  { int o = t / 20, i = t % 20; wT0[i * 32 + o] = w0[t]; }
    for (int t = tid; t < 1024; t += 256) { int o = t >> 5, i = t & 31; wT1[i * 32 + o] = w1[t]; wT2[i * 32 + o] = w2[t]; }
    for (int t = tid; t < 2048; t += 256) { int o = t >> 5, i = t & 31; wT3[i * 64 + o] = w3[t]; }
    if (tid < 32) { sb0[tid] = b0[tid]; sb1[tid] = b1[tid]; sb2[tid] = b2[tid]; }
    if (tid < 64) sb3[tid] = b3[tid];
    __syncthreads();

    int e = blockIdx.x * 256 + tid;
    int use64 = g_idx64;
    int s = load_idx(ei, e, use64);
    int d = load_idx(ei, E_N + e, use64);

    float x[20];
    {
        float4 v = *(const float4*)&ea[e * 4];
        x[0] = v.x; x[1] = v.y; x[2] = v.z; x[3] = v.w;
        v = *(const float4*)&feat[s * 8];     x[4] = v.x;  x[5] = v.y;  x[6] = v.z;  x[7] = v.w;
        v = *(const float4*)&feat[s * 8 + 4]; x[8] = v.x;  x[9] = v.y;  x[10] = v.z; x[11] = v.w;
        v = *(const float4*)&feat[d * 8];     x[12] = v.x; x[13] = v.y; x[14] = v.z; x[15] = v.w;
        v = *(const float4*)&feat[d * 8 + 4]; x[16] = v.x; x[17] = v.y; x[18] = v.z; x[19] = v.w;
    }

    float h[32], h2[32];
    // layer 0: 20 -> 32
    #pragma unroll
    for (int o = 0; o < 32; o++) h[o] = sb0[o];
    #pragma unroll
    for (int i = 0; i < 20; i++) {
        float xi = x[i];
        #pragma unroll
        for (int o = 0; o < 32; o += 4) {
            float4 w = *(const float4*)&wT0[i * 32 + o];
            h[o] += xi * w.x; h[o+1] += xi * w.y; h[o+2] += xi * w.z; h[o+3] += xi * w.w;
        }
    }
    #pragma unroll
    for (int o = 0; o < 32; o++) h[o] = fmaxf(h[o], 0.f);

    // layer 1: 32 -> 32
    #pragma unroll
    for (int o = 0; o < 32; o++) h2[o] = sb1[o];
    #pragma unroll
    for (int i = 0; i < 32; i++) {
        float xi = h[i];
        #pragma unroll
        for (int o = 0; o < 32; o += 4) {
            float4 w = *(const float4*)&wT1[i * 32 + o];
            h2[o] += xi * w.x; h2[o+1] += xi * w.y; h2[o+2] += xi * w.z; h2[o+3] += xi * w.w;
        }
    }
    #pragma unroll
    for (int o = 0; o < 32; o++) h2[o] = fmaxf(h2[o], 0.f);

    // layer 2: 32 -> 32
    #pragma unroll
    for (int o = 0; o < 32; o++) h[o] = sb2[o];
    #pragma unroll
    for (int i = 0; i < 32; i++) {
        float xi = h2[i];
        #pragma unroll
        for (int o = 0; o < 32; o += 4) {
            float4 w = *(const float4*)&wT2[i * 32 + o];
            h[o] += xi * w.x; h[o+1] += xi * w.y; h[o+2] += xi * w.z; h[o+3] += xi * w.w;
        }
    }
    #pragma unroll
    for (int o = 0; o < 32; o++) h[o] = fmaxf(h[o], 0.f);

    // layer 3: 32 -> 64 (no relu)
    float o64[64];
    #pragma unroll
    for (int o = 0; o < 64; o++) o64[o] = sb3[o];
    #pragma unroll
    for (int i = 0; i < 32; i++) {
        float xi = h[i];
        #pragma unroll
        for (int o = 0; o < 64; o += 4) {
            float4 w = *(const float4*)&wT3[i * 64 + o];
            o64[o] += xi * w.x; o64[o+1] += xi * w.y; o64[o+2] += xi * w.z; o64[o+3] += xi * w.w;
        }
    }
    #pragma unroll
    for (int c = 0; c < 64; c += 4) {
        float4 v; v.x = o64[c]; v.y = o64[c+1]; v.z = o64[c+2]; v.w = o64[c+3];
        *(float4*)&g_evals[e * 64 + c] = v;
    }
}

// -------- walk contraction: coalesced via g_mtrT, f32x2 packed over t --------
__global__ void k_walk(const void* __restrict__ ei) {
    int k = blockIdx.x;
    int tid = threadIdx.x;
    __shared__ __align__(16) float sM[8 * 64];
    __shared__ int ssrc[8];
    int cnt = min(g_cnt[k], CAP);
    int use64 = g_idx64;

    u64 acc[3][4];
    #pragma unroll
    for (int r = 0; r < 3; r++)
        #pragma unroll
        for (int t = 0; t < 4; t++) acc[r][t] = 0ULL;

    for (int base = 0; base < cnt; base += 8) {
        int nc = min(8, cnt - base);
        __syncthreads();
        for (int t = tid; t < nc * 64; t += 256) {
            int e = g_list[k * CAP + base + (t >> 6)];
            sM[t] = g_evals[e * 64 + (t & 63)];
        }
        if (tid < nc) ssrc[tid] = load_idx(ei, g_list[k * CAP + base + tid], use64);
        __syncthreads();

        for (int c = 0; c < nc; c++) {
            int s = ssrc[c];
            float av[3][8];
            #pragma unroll
            for (int r = 0; r < 3; r++) {
                int i = tid + (r << 8);
                const float4* p = (const float4*)&g_mtrT[(s * N + i) * 8];  // coalesced
                float4 v0 = p[0], v1 = p[1];
                av[r][0] = v0.x; av[r][1] = v0.y; av[r][2] = v0.z; av[r][3] = v0.w;
                av[r][4] = v1.x; av[r][5] = v1.y; av[r][6] = v1.z; av[r][7] = v1.w;
            }
            #pragma unroll
            for (int cc = 0; cc < 8; cc++) {
                const ulonglong2* mp = (const ulonglong2*)&sM[c * 64 + cc * 8];
                ulonglong2 ma = mp[0], mb = mp[1];
                #pragma unroll
                for (int r = 0; r < 3; r++) {
                    u64 dv = pk2(av[r][cc], av[r][cc]);
                    acc[r][0] = fma2(dv, ma.x, acc[r][0]);
                    acc[r][1] = fma2(dv, ma.y, acc[r][1]);
                    acc[r][2] = fma2(dv, mb.x, acc[r][2]);
                    acc[r][3] = fma2(dv, mb.y, acc[r][3]);
                }
            }
        }
    }
    u64 eighth = pk2(0.125f, 0.125f);
    #pragma unroll
    for (int r = 0; r < 3; r++) {
        int i = tid + (r << 8);
        float4 o0, o1;
        upk2(mul2(acc[r][0], eighth), o0.x, o0.y);
        upk2(mul2(acc[r][1], eighth), o0.z, o0.w);
        upk2(mul2(acc[r][2], eighth), o1.x, o1.y);
        upk2(mul2(acc[r][3], eighth), o1.z, o1.w);
        *(float4*)&g_mtr1[(i * N + k) * 8]     = o0;
        *(float4*)&g_mtr1[(i * N + k) * 8 + 4] = o1;
    }
    if (tid == 0) g_cnt[k] = 0;               // self-reset for next replay
}

// -------- output MLP: 2 rows/thread, f32x2, j-grouped layer-0 loads --------
__global__ void __launch_bounds__(128, 3) k_out(
        const float* __restrict__ mtr, const float* __restrict__ feat,
        float* __restrict__ out,
        const float* __restrict__ w0, const float* __restrict__ b0,
        const float* __restrict__ w1, const float* __restrict__ b1,
        const float* __restrict__ w2, const float* __restrict__ b2,
        const float* __restrict__ w3, const float* __restrict__ b3) {
    // duplicated weight packs, transposed: wd[j*OUT + o] = (w[o][j], w[o][j])
    __shared__ __align__(16) u64 wd0[33 * 32], wd1[32 * 32], wd2[32 * 32], wd3[32 * 8];
    __shared__ __align__(16) u64 bd0[32], bd1[32], bd2[32], bd3[8], fi[8];
    int tid = threadIdx.x;
    for (int t = tid; t < 1056; t += 128) { int j = t >> 5, o = t & 31; float w = w0[o * 33 + j]; wd0[t] = pk2(w, w); }
    for (int t = tid; t < 1024; t += 128) {
        int j = t >> 5, o = t & 31;
        float wa = w1[o * 32 + j]; wd1[t] = pk2(wa, wa);
        float wb = w2[o * 32 + j]; wd2[t] = pk2(wb, wb);
    }
    for (int t = tid; t < 256; t += 128) { int j = t >> 3, o = t & 7; float w = w3[o * 32 + j]; wd3[t] = pk2(w, w); }
    if (tid < 32) {
        float v;
        v = b0[tid]; bd0[tid] = pk2(v, v);
        v = b1[tid]; bd1[tid] = pk2(v, v);
        v = b2[tid]; bd2[tid] = pk2(v, v);
        if (tid < 8) { v = b3[tid]; bd3[tid] = pk2(v, v); }
    }
    if (tid < 8) { float v = feat[blockIdx.y * 8 + tid]; fi[tid] = pk2(v, v); }
    __syncthreads();

    int i  = blockIdx.y;
    int k1 = blockIdx.x * 256 + tid;
    int k2 = k1 + 128;
    int base1 = (i * N + k1) * 8, base2 = (i * N + k2) * 8;
    int bT1 = (k1 * N + i) * 8, bT2 = (k2 * N + i) * 8;

    u64 acc[32], h[32];
    {
        const ulonglong2* B = (const ulonglong2*)bd0;
        #pragma unroll
        for (int oo = 0; oo < 16; oo++) { ulonglong2 b = B[oo]; acc[2*oo] = b.x; acc[2*oo+1] = b.y; }
    }
    const ulonglong2* W0 = (const ulonglong2*)wd0;
    u64 xg[8];

    #define L0_GROUP(JBASE)                                              \
        _Pragma("unroll")                                                \
        for (int jj = 0; jj < 8; jj++) {                                 \
            u64 xj = xg[jj];                                             \
            _Pragma("unroll")                                            \
            for (int oo = 0; oo < 16; oo++) {                            \
                ulonglong2 w = W0[(JBASE + jj) * 16 + oo];               \
                acc[2*oo]   = fma2(xj, w.x, acc[2*oo]);                  \
                acc[2*oo+1] = fma2(xj, w.y, acc[2*oo+1]);                \
            }                                                            \
        }

    // j 0..7: mtr1 rows (row-major)
    {
        float4 a0 = *(const float4*)&g_mtr1[base1], a1 = *(const float4*)&g_mtr1[base1 + 4];
        float4 c0 = *(const float4*)&g_mtr1[base2], c1 = *(const float4*)&g_mtr1[base2 + 4];
        xg[0] = pk2(a0.x, c0.x); xg[1] = pk2(a0.y, c0.y); xg[2] = pk2(a0.z, c0.z); xg[3] = pk2(a0.w, c0.w);
        xg[4] = pk2(a1.x, c1.x); xg[5] = pk2(a1.y, c1.y); xg[6] = pk2(a1.z, c1.z); xg[7] = pk2(a1.w, c1.w);
    }
    L0_GROUP(0)
    // j 8..15: mtr1 transposed rows
    {
        float4 a0 = *(const float4*)&g_mtr1[bT1], a1 = *(const float4*)&g_mtr1[bT1 + 4];
        float4 c0 = *(const float4*)&g_mtr1[bT2], c1 = *(const float4*)&g_mtr1[bT2 + 4];
        xg[0] = pk2(a0.x, c0.x); xg[1] = pk2(a0.y, c0.y); xg[2] = pk2(a0.z, c0.z); xg[3] = pk2(a0.w, c0.w);
        xg[4] = pk2(a1.x, c1.x); xg[5] = pk2(a1.y, c1.y); xg[6] = pk2(a1.z, c1.z); xg[7] = pk2(a1.w, c1.w);
    }
    L0_GROUP(8)
    // j 16..23: feat[k]
    {
        float4 a0 = *(const float4*)&feat[k1 * 8], a1 = *(const float4*)&feat[k1 * 8 + 4];
        float4 c0 = *(const float4*)&feat[k2 * 8], c1 = *(const float4*)&feat[k2 * 8 + 4];
        xg[0] = pk2(a0.x, c0.x); xg[1] = pk2(a0.y, c0.y); xg[2] = pk2(a0.z, c0.z); xg[3] = pk2(a0.w, c0.w);
        xg[4] = pk2(a1.x, c1.x); xg[5] = pk2(a1.y, c1.y); xg[6] = pk2(a1.z, c1.z); xg[7] = pk2(a1.w, c1.w);
    }
    L0_GROUP(16)
    // j 24..31: feat[i] from smem (uniform per block row)
    {
        const ulonglong2* F = (const ulonglong2*)fi;
        ulonglong2 f0 = F[0], f1 = F[1], f2 = F[2], f3 = F[3];
        xg[0] = f0.x; xg[1] = f0.y; xg[2] = f1.x; xg[3] = f1.y;
        xg[4] = f2.x; xg[5] = f2.y; xg[6] = f3.x; xg[7] = f3.y;
    }
    L0_GROUP(24)
    // j 32: eye
    {
        u64 xj = pk2(i == k1 ? 1.f : 0.f, i == k2 ? 1.f : 0.f);
        #pragma unroll
        for (int oo = 0; oo < 16; oo++) {
            ulonglong2 w = W0[32 * 16 + oo];
            acc[2*oo]   = fma2(xj, w.x, acc[2*oo]);
            acc[2*oo+1] = fma2(xj, w.y, acc[2*oo+1]);
        }
    }
    #undef L0_GROUP
    #pragma unroll
    for (int o = 0; o < 32; o++) h[o] = relu2(acc[o]);

    // layer 1: 32 -> 32
    {
        const ulonglong2* B = (const ulonglong2*)bd1;
        #pragma unroll
        for (int oo = 0; oo < 16; oo++) { ulonglong2 b = B[oo]; acc[2*oo] = b.x; acc[2*oo+1] = b.y; }
        const ulonglong2* W = (const ulonglong2*)wd1;
        #pragma unroll
        for (int j = 0; j < 32; j++) {
            u64 xj = h[j];
            #pragma unroll
            for (int oo = 0; oo < 16; oo++) {
                ulonglong2 w = W[j * 16 + oo];
                acc[2*oo]   = fma2(xj, w.x, acc[2*oo]);
                acc[2*oo+1] = fma2(xj, w.y, acc[2*oo+1]);
            }
        }
        #pragma unroll
        for (int o = 0; o < 32; o++) acc[o] = relu2(acc[o]);
    }
    // layer 2: 32 -> 32
    {
        const ulonglong2* B = (const ulonglong2*)bd2;
        #pragma unroll
        for (int oo = 0; oo < 16; oo++) { ulonglong2 b = B[oo]; h[2*oo] = b.x; h[2*oo+1] = b.y; }
        const ulonglong2* W = (const ulonglong2*)wd2;
        #pragma unroll
        for (int j = 0; j < 32; j++) {
            u64 xj = acc[j];
            #pragma unroll
            for (int oo = 0; oo < 16; oo++) {
                ulonglong2 w = W[j * 16 + oo];
                h[2*oo]   = fma2(xj, w.x, h[2*oo]);
                h[2*oo+1] = fma2(xj, w.y, h[2*oo+1]);
            }
        }
        #pragma unroll
        for (int o = 0; o < 32; o++) h[o] = relu2(h[o]);
    }
    // layer 3: 32 -> 8
    u64 y[8];
    {
        const ulonglong2* B = (const ulonglong2*)bd3;
        #pragma unroll
        for (int oo = 0; oo < 4; oo++) { ulonglong2 b = B[oo]; y[2*oo] = b.x; y[2*oo+1] = b.y; }
        const ulonglong2* W = (const ulonglong2*)wd3;
        #pragma unroll
        for (int j = 0; j < 32; j++) {
            u64 xj = h[j];
            #pragma unroll
            for (int oo = 0; oo < 4; oo++) {
                ulonglong2 w = W[j * 4 + oo];
                y[2*oo]   = fma2(xj, w.x, y[2*oo]);
                y[2*oo+1] = fma2(xj, w.y, y[2*oo+1]);
            }
        }
    }
    // residual add + store both rows
    {
        float yr1[8], yr2[8];
        #pragma unroll
        for (int c = 0; c < 8; c++) upk2(y[c], yr1[c], yr2[c]);
        float4 m0 = *(const float4*)&mtr[base1], m1 = *(const float4*)&mtr[base1 + 4];
        float4 o0, o1;
        o0.x = m0.x + yr1[0]; o0.y = m0.y + yr1[1]; o0.z = m0.z + yr1[2]; o0.w = m0.w + yr1[3];
        o1.x = m1.x + yr1[4]; o1.y = m1.y + yr1[5]; o1.z = m1.z + yr1[6]; o1.w = m1.w + yr1[7];
        *(float4*)&out[base1] = o0; *(float4*)&out[base1 + 4] = o1;
        m0 = *(const float4*)&mtr[base2]; m1 = *(const float4*)&mtr[base2 + 4];
        o0.x = m0.x + yr2[0]; o0.y = m0.y + yr2[1]; o0.z = m0.z + yr2[2]; o0.w = m0.w + yr2[3];
        o1.x = m1.x + yr2[4]; o1.y = m1.y + yr2[5]; o1.z = m1.z + yr2[6]; o1.w = m1.w + yr2[7];
        *(float4*)&out[base2] = o0; *(float4*)&out[base2 + 4] = o1;
    }
}

extern "C" void kernel_launch(void* const* d_in, const int* in_sizes, int n_in,
                              void* d_out, int out_size) {
    const float* mtr  = (const float*)d_in[0];
    const float* feat = (const float*)d_in[1];
    const void*  ei   = d_in[2];
    const float* ea   = (const float*)d_in[3];
    const float* ew0 = (const float*)d_in[4],  *eb0 = (const float*)d_in[5];
    const float* ew1 = (const float*)d_in[6],  *eb1 = (const float*)d_in[7];
    const float* ew2 = (const float*)d_in[8],  *eb2 = (const float*)d_in[9];
    const float* ew3 = (const float*)d_in[10], *eb3 = (const float*)d_in[11];
    const float* ow0 = (const float*)d_in[12], *ob0 = (const float*)d_in[13];
    const float* ow1 = (const float*)d_in[14], *ob1 = (const float*)d_in[15];
    const float* ow2 = (const float*)d_in[16], *ob2 = (const float*)d_in[17];
    const float* ow3 = (const float*)d_in[18], *ob3 = (const float*)d_in[19];
    float* out = (float*)d_out;

    k_pre<<<673, 256>>>((const int*)ei, mtr, ei);
    k_edge<<<192, 256>>>(ei, ea, feat, ew0, eb0, ew1, eb1, ew2, eb2, ew3, eb3);
    k_walk<<<N, 256>>>(ei);
    dim3 g(3, N);
    k_out<<<g, 128>>>(mtr, feat, out, ow0, ob0, ow1, ob1, ow2, ob2, ow3, ob3);
}

// round 17
// speedup vs baseline: 1.2933x; 1.2301x over previous
#include <cuda_runtime.h>

#define N 768
#define E_N 24576
#define CAP 128

// -------- device scratch (zero-initialized at module load; self-resetting) --------
static __device__ int   g_winner[N * N];             // 0 = empty, else winning e+1
static __device__ int   g_cnt[N];
static __device__ int   g_list[N * CAP];
static __device__ float g_evals[E_N * 64];           // edge MLP out [E,8,8]
static __device__ float g_mtr1[N * N * 8];           // walk result
static __device__ float g_mtrT[N * N * 8];           // mtr transposed: [j][i][c]
static __device__ int   g_idx64;

typedef unsigned long long u64;

// -------- f32x2 helpers --------
__device__ __forceinline__ u64 pk2(float lo, float hi) {
    u64 r;
    asm("mov.b64 %0, {%1, %2};" : "=l"(r) : "r"(__float_as_uint(lo)), "r"(__float_as_uint(hi)));
    return r;
}
__device__ __forceinline__ void upk2(u64 p, float& lo, float& hi) {
    unsigned a, b;
    asm("mov.b64 {%0, %1}, %2;" : "=r"(a), "=r"(b) : "l"(p));
    lo = __uint_as_float(a); hi = __uint_as_float(b);
}
__device__ __forceinline__ u64 swp2(u64 p) {
    unsigned a, b;
    asm("mov.b64 {%0, %1}, %2;" : "=r"(a), "=r"(b) : "l"(p));
    u64 r;
    asm("mov.b64 %0, {%1, %2};" : "=l"(r) : "r"(b), "r"(a));
    return r;
}
__device__ __forceinline__ u64 fma2(u64 a, u64 b, u64 c) {
    u64 d;
    asm("fma.rn.f32x2 %0, %1, %2, %3;" : "=l"(d) : "l"(a), "l"(b), "l"(c));
    return d;
}
__device__ __forceinline__ u64 mul2(u64 a, u64 b) {
    u64 d;
    asm("mul.rn.f32x2 %0, %1, %2;" : "=l"(d) : "l"(a), "l"(b));
    return d;
}
__device__ __forceinline__ u64 relu2(u64 p) {
    float lo, hi; upk2(p, lo, hi);
    return pk2(fmaxf(lo, 0.f), fmaxf(hi, 0.f));
}

__device__ __forceinline__ int load_idx(const void* ei, int pos, int use64) {
    if (use64) return (int)((const long long*)ei)[pos];
    return ((const int*)ei)[pos];
}

// -------- k_pre: winner (blocks 0..95, block-local dtype vote) +
//          tiled transpose (96..671) + global dtype detect (672) --------
__global__ void k_pre(const int* __restrict__ ei32, const float* __restrict__ mtr,
                      const void* __restrict__ ei) {
    int b = blockIdx.x;
    int tid = threadIdx.x;
    if (b < 96) {
        int e = b * 256 + tid;
        int any = __syncthreads_or(ei32[2 * e + 1] != 0);
        int use64 = (any == 0) ? 1 : 0;
        int s = load_idx(ei, e, use64);
        int d = load_idx(ei, E_N + e, use64);
        atomicMax(&g_winner[s * N + d], e + 1);
        return;
    }
    if (b == 672) {
        __shared__ int any;
        if (tid == 0) any = 0;
        __syncthreads();
        for (int j = tid * 2 + 1; j < 4096; j += 512)
            if (ei32[j] != 0) any = 1;
        __syncthreads();
        if (tid == 0) g_idx64 = (any == 0) ? 1 : 0;
        return;
    }
    __shared__ __align__(16) float sm[32 * 264];
    int t = b - 96;
    int I0 = (t / 24) * 32, J0 = (t % 24) * 32;
    #pragma unroll
    for (int q = 0; q < 4; q++) {
        int idx = q * 256 + tid;
        int il = idx >> 5, jl = idx & 31;
        const float4* p = (const float4*)&mtr[((I0 + il) * N + (J0 + jl)) * 8];
        float4 v0 = p[0], v1 = p[1];
        float* s = &sm[jl * 264 + il * 8];
        *(float4*)s = v0; *(float4*)(s + 4) = v1;
    }
    __syncthreads();
    #pragma unroll
    for (int q = 0; q < 4; q++) {
        int idx = q * 256 + tid;
        int jl = idx >> 5, il = idx & 31;
        const float* s = &sm[jl * 264 + il * 8];
        float4 v0 = *(const float4*)s, v1 = *(const float4*)(s + 4);
        float4* qp = (float4*)&g_mtrT[((J0 + jl) * N + (I0 + il)) * 8];
        qp[0] = v0; qp[1] = v1;
    }
}

// -------- edge MLP (blocks 0..95) + winner-build & cell reset (blocks 96..191) --------
__global__ void k_edge(const void* __restrict__ ei, const float* __restrict__ ea,
                       const float* __restrict__ feat,
                       const float* __restrict__ w0, const float* __restrict__ b0,
                       const float* __restrict__ w1, const float* __restrict__ b1,
                       const float* __restrict__ w2, const float* __restrict__ b2,
                       const float* __restrict__ w3, const float* __restrict__ b3) {
    if (blockIdx.x >= 96) {
        int e = (blockIdx.x - 96) * 256 + threadIdx.x;
        int use64 = g_idx64;
        int s = load_idx(ei, e, use64);
        int d = load_idx(ei, E_N + e, use64);
        int cell = s * N + d;
        if (g_winner[cell] == e + 1) {
            int slot = atomicAdd(&g_cnt[d], 1);
            if (slot < CAP) g_list[d * CAP + slot] = e;
            g_winner[cell] = 0;
        }
        return;
    }
    __shared__ __align__(16) float wT0[20 * 32], wT1[32 * 32], wT2[32 * 32], wT3[32 * 64];
    __shared__ float sb0[32], sb1[32], sb2[32], sb3[64];
    int tid = threadIdx.x;
    for (int t = tid; t < 640; t += 256)  { int o = t / 20, i = t % 20; wT0[i * 32 + o] = w0[t]; }
    for (int t = tid; t < 1024; t += 256) { int o = t >> 5, i = t & 31; wT1[i * 32 + o] = w1[t]; wT2[i * 32 + o] = w2[t]; }
    for (int t = tid; t < 2048; t += 256) { int o = t >> 5, i = t & 31; wT3[i * 64 + o] = w3[t]; }
    if (tid < 32) { sb0[tid] = b0[tid]; sb1[tid] = b1[tid]; sb2[tid] = b2[tid]; }
    if (tid < 64) sb3[tid] = b3[tid];
    __syncthreads();

    int e = blockIdx.x * 256 + tid;
    int use64 = g_idx64;
    int s = load_idx(ei, e, use64);
    int d = load_idx(ei, E_N + e, use64);

    float x[20];
    {
        float4 v = *(const float4*)&ea[e * 4];
        x[0] = v.x; x[1] = v.y; x[2] = v.z; x[3] = v.w;
        v = *(const float4*)&feat[s * 8];     x[4] = v.x;  x[5] = v.y;  x[6] = v.z;  x[7] = v.w;
        v = *(const float4*)&feat[s * 8 + 4]; x[8] = v.x;  x[9] = v.y;  x[10] = v.z; x[11] = v.w;
        v = *(const float4*)&feat[d * 8];     x[12] = v.x; x[13] = v.y; x[14] = v.z; x[15] = v.w;
        v = *(const float4*)&feat[d * 8 + 4]; x[16] = v.x; x[17] = v.y; x[18] = v.z; x[19] = v.w;
    }

    float h[32], h2[32];
    #pragma unroll
    for (int o = 0; o < 32; o++) h[o] = sb0[o];
    #pragma unroll
    for (int i = 0; i < 20; i++) {
        float xi = x[i];
        #pragma unroll
        for (int o = 0; o < 32; o += 4) {
            float4 w = *(const float4*)&wT0[i * 32 + o];
            h[o] += xi * w.x; h[o+1] += xi * w.y; h[o+2] += xi * w.z; h[o+3] += xi * w.w;
        }
    }
    #pragma unroll
    for (int o = 0; o < 32; o++) h[o] = fmaxf(h[o], 0.f);

    #pragma unroll
    for (int o = 0; o < 32; o++) h2[o] = sb1[o];
    #pragma unroll
    for (int i = 0; i < 32; i++) {
        float xi = h[i];
        #pragma unroll
        for (int o = 0; o < 32; o += 4) {
            float4 w = *(const float4*)&wT1[i * 32 + o];
            h2[o] += xi * w.x; h2[o+1] += xi * w.y; h2[o+2] += xi * w.z; h2[o+3] += xi * w.w;
        }
    }
    #pragma unroll
    for (int o = 0; o < 32; o++) h2[o] = fmaxf(h2[o], 0.f);

    #pragma unroll
    for (int o = 0; o < 32; o++) h[o] = sb2[o];
    #pragma unroll
    for (int i = 0; i < 32; i++) {
        float xi = h2[i];
        #pragma unroll
        for (int o = 0; o < 32; o += 4) {
            float4 w = *(const float4*)&wT2[i * 32 + o];
            h[o] += xi * w.x; h[o+1] += xi * w.y; h[o+2] += xi * w.z; h[o+3] += xi * w.w;
        }
    }
    #pragma unroll
    for (int o = 0; o < 32; o++) h[o] = fmaxf(h[o], 0.f);

    float o64[64];
    #pragma unroll
    for (int o = 0; o < 64; o++) o64[o] = sb3[o];
    #pragma unroll
    for (int i = 0; i < 32; i++) {
        float xi = h[i];
        #pragma unroll
        for (int o = 0; o < 64; o += 4) {
            float4 w = *(const float4*)&wT3[i * 64 + o];
            o64[o] += xi * w.x; o64[o+1] += xi * w.y; o64[o+2] += xi * w.z; o64[o+3] += xi * w.w;
        }
    }
    #pragma unroll
    for (int c = 0; c < 64; c += 4) {
        float4 v; v.x = o64[c]; v.y = o64[c+1]; v.z = o64[c+2]; v.w = o64[c+3];
        *(float4*)&g_evals[e * 64 + c] = v;
    }
}

// -------- walk contraction: coalesced via g_mtrT, f32x2 packed over t --------
__global__ void k_walk(const void* __restrict__ ei) {
    int k = blockIdx.x;
    int tid = threadIdx.x;
    __shared__ __align__(16) float sM[8 * 64];
    __shared__ int ssrc[8];
    int cnt = min(g_cnt[k], CAP);
    int use64 = g_idx64;

    u64 acc[3][4];
    #pragma unroll
    for (int r = 0; r < 3; r++)
        #pragma unroll
        for (int t = 0; t < 4; t++) acc[r][t] = 0ULL;

    for (int base = 0; base < cnt; base += 8) {
        int nc = min(8, cnt - base);
        __syncthreads();
        for (int t = tid; t < nc * 64; t += 256) {
            int e = g_list[k * CAP + base + (t >> 6)];
            sM[t] = g_evals[e * 64 + (t & 63)];
        }
        if (tid < nc) ssrc[tid] = load_idx(ei, g_list[k * CAP + base + tid], use64);
        __syncthreads();

        for (int c = 0; c < nc; c++) {
            int s = ssrc[c];
            float av[3][8];
            #pragma unroll
            for (int r = 0; r < 3; r++) {
                int i = tid + (r << 8);
                const float4* p = (const float4*)&g_mtrT[(s * N + i) * 8];
                float4 v0 = p[0], v1 = p[1];
                av[r][0] = v0.x; av[r][1] = v0.y; av[r][2] = v0.z; av[r][3] = v0.w;
                av[r][4] = v1.x; av[r][5] = v1.y; av[r][6] = v1.z; av[r][7] = v1.w;
            }
            #pragma unroll
            for (int cc = 0; cc < 8; cc++) {
                const ulonglong2* mp = (const ulonglong2*)&sM[c * 64 + cc * 8];
                ulonglong2 ma = mp[0], mb = mp[1];
                #pragma unroll
                for (int r = 0; r < 3; r++) {
                    u64 dv = pk2(av[r][cc], av[r][cc]);
                    acc[r][0] = fma2(dv, ma.x, acc[r][0]);
                    acc[r][1] = fma2(dv, ma.y, acc[r][1]);
                    acc[r][2] = fma2(dv, mb.x, acc[r][2]);
                    acc[r][3] = fma2(dv, mb.y, acc[r][3]);
                }
            }
        }
    }
    u64 eighth = pk2(0.125f, 0.125f);
    #pragma unroll
    for (int r = 0; r < 3; r++) {
        int i = tid + (r << 8);
        float4 o0, o1;
        upk2(mul2(acc[r][0], eighth), o0.x, o0.y);
        upk2(mul2(acc[r][1], eighth), o0.z, o0.w);
        upk2(mul2(acc[r][2], eighth), o1.x, o1.y);
        upk2(mul2(acc[r][3], eighth), o1.z, o1.w);
        *(float4*)&g_mtr1[(i * N + k) * 8]     = o0;
        *(float4*)&g_mtr1[(i * N + k) * 8 + 4] = o1;
    }
    if (tid == 0) g_cnt[k] = 0;
}

// -------- output MLP v3: mixed-pair f32x2 (no weight duplication) --------
// Weight packs: wp[j][p] = (w[2p][j], w[2p+1][j]).  For x=(r1,r2), xs=(r2,r1):
//   acc_m[p] += x  * wp  -> (r1*n2p,  r2*n2p1)
//   acc_s[p] += xs * wp  -> (r2*n2p,  r1*n2p1)
// Un-mix at relu: h[2p]=(am.lo,as.lo), h[2p+1]=(as.hi,am.hi).
__global__ void __launch_bounds__(128, 3) k_out(
        const float* __restrict__ mtr, const float* __restrict__ feat,
        float* __restrict__ out,
        const float* __restrict__ w0, const float* __restrict__ b0,
        const float* __restrict__ w1, const float* __restrict__ b1,
        const float* __restrict__ w2, const float* __restrict__ b2,
        const float* __restrict__ w3, const float* __restrict__ b3) {
    __shared__ __align__(16) u64 wp0[33 * 16], wp1[32 * 16], wp2[32 * 16], wp3[32 * 4];
    __shared__ __align__(16) u64 bp0[16], bp1[16], bp2[16], bp3[4], fi[8];
    int tid = threadIdx.x;
    for (int t = tid; t < 528; t += 128) {
        int j = t >> 4, p = t & 15;
        wp0[t] = pk2(w0[(2 * p) * 33 + j], w0[(2 * p + 1) * 33 + j]);
    }
    for (int t = tid; t < 512; t += 128) {
        int j = t >> 4, p = t & 15;
        wp1[t] = pk2(w1[(2 * p) * 32 + j], w1[(2 * p + 1) * 32 + j]);
        wp2[t] = pk2(w2[(2 * p) * 32 + j], w2[(2 * p + 1) * 32 + j]);
    }
    if (tid < 128) {
        int j = tid >> 2, p = tid & 3;
        wp3[tid] = pk2(w3[(2 * p) * 32 + j], w3[(2 * p + 1) * 32 + j]);
    }
    if (tid < 16) {
        bp0[tid] = pk2(b0[2 * tid], b0[2 * tid + 1]);
        bp1[tid] = pk2(b1[2 * tid], b1[2 * tid + 1]);
        bp2[tid] = pk2(b2[2 * tid], b2[2 * tid + 1]);
        if (tid < 4) bp3[tid] = pk2(b3[2 * tid], b3[2 * tid + 1]);
    }
    if (tid < 8) { float v = feat[blockIdx.y * 8 + tid]; fi[tid] = pk2(v, v); }
    __syncthreads();

    int i  = blockIdx.y;
    int k1 = blockIdx.x * 256 + tid;
    int k2 = k1 + 128;
    int base1 = (i * N + k1) * 8, base2 = (i * N + k2) * 8;
    int bT1 = (k1 * N + i) * 8, bT2 = (k2 * N + i) * 8;

    u64 am[16], as_[16], h[32];
    {
        const ulonglong2* B = (const ulonglong2*)bp0;
        #pragma unroll
        for (int pp = 0; pp < 8; pp++) {
            ulonglong2 b = B[pp];
            am[2*pp] = b.x; am[2*pp+1] = b.y;
            as_[2*pp] = b.x; as_[2*pp+1] = b.y;
        }
    }
    const ulonglong2* W0 = (const ulonglong2*)wp0;
    u64 xg[8];

    #define PAIR_J(W, JIDX, XJ)                                          \
        {                                                                \
            u64 _xj = (XJ);                                              \
            u64 _xs = swp2(_xj);                                         \
            _Pragma("unroll")                                            \
            for (int pp = 0; pp < 8; pp++) {                             \
                ulonglong2 w = (W)[(JIDX) * 8 + pp];                     \
                am[2*pp]    = fma2(_xj, w.x, am[2*pp]);                  \
                as_[2*pp]   = fma2(_xs, w.x, as_[2*pp]);                 \
                am[2*pp+1]  = fma2(_xj, w.y, am[2*pp+1]);                \
                as_[2*pp+1] = fma2(_xs, w.y, as_[2*pp+1]);               \
            }                                                            \
        }

    #define L0_GROUP(JBASE)                                              \
        _Pragma("unroll")                                                \
        for (int jj = 0; jj < 8; jj++) PAIR_J(W0, JBASE + jj, xg[jj])

    // j 0..7: mtr1 rows
    {
        float4 a0 = *(const float4*)&g_mtr1[base1], a1 = *(const float4*)&g_mtr1[base1 + 4];
        float4 c0 = *(const float4*)&g_mtr1[base2], c1 = *(const float4*)&g_mtr1[base2 + 4];
        xg[0] = pk2(a0.x, c0.x); xg[1] = pk2(a0.y, c0.y); xg[2] = pk2(a0.z, c0.z); xg[3] = pk2(a0.w, c0.w);
        xg[4] = pk2(a1.x, c1.x); xg[5] = pk2(a1.y, c1.y); xg[6] = pk2(a1.z, c1.z); xg[7] = pk2(a1.w, c1.w);
    }
    L0_GROUP(0)
    // j 8..15: mtr1 transposed rows
    {
        float4 a0 = *(const float4*)&g_mtr1[bT1], a1 = *(const float4*)&g_mtr1[bT1 + 4];
        float4 c0 = *(const float4*)&g_mtr1[bT2], c1 = *(const float4*)&g_mtr1[bT2 + 4];
        xg[0] = pk2(a0.x, c0.x); xg[1] = pk2(a0.y, c0.y); xg[2] = pk2(a0.z, c0.z); xg[3] = pk2(a0.w, c0.w);
        xg[4] = pk2(a1.x, c1.x); xg[5] = pk2(a1.y, c1.y); xg[6] = pk2(a1.z, c1.z); xg[7] = pk2(a1.w, c1.w);
    }
    L0_GROUP(8)
    // j 16..23: feat[k]
    {
        float4 a0 = *(const float4*)&feat[k1 * 8], a1 = *(const float4*)&feat[k1 * 8 + 4];
        float4 c0 = *(const float4*)&feat[k2 * 8], c1 = *(const float4*)&feat[k2 * 8 + 4];
        xg[0] = pk2(a0.x, c0.x); xg[1] = pk2(a0.y, c0.y); xg[2] = pk2(a0.z, c0.z); xg[3] = pk2(a0.w, c0.w);
        xg[4] = pk2(a1.x, c1.x); xg[5] = pk2(a1.y, c1.y); xg[6] = pk2(a1.z, c1.z); xg[7] = pk2(a1.w, c1.w);
    }
    L0_GROUP(16)
    // j 24..31: feat[i] (uniform; swap is identity but generic path is fine)
    {
        const ulonglong2* F = (const ulonglong2*)fi;
        ulonglong2 f0 = F[0], f1 = F[1], f2 = F[2], f3 = F[3];
        xg[0] = f0.x; xg[1] = f0.y; xg[2] = f1.x; xg[3] = f1.y;
        xg[4] = f2.x; xg[5] = f2.y; xg[6] = f3.x; xg[7] = f3.y;
    }
    L0_GROUP(24)
    // j 32: eye
    PAIR_J(W0, 32, pk2(i == k1 ? 1.f : 0.f, i == k2 ? 1.f : 0.f))
    #undef L0_GROUP

    // relu + un-mix into h (h[j] = (r1, r2) for neuron j)
    #define UNMIX_RELU()                                                 \
        _Pragma("unroll")                                                \
        for (int p = 0; p < 16; p++) {                                   \
            u64 a = relu2(am[p]), b = relu2(as_[p]);                     \
            float _a, _b, _c, _d;                                        \
            upk2(a, _a, _b); upk2(b, _c, _d);                            \
            h[2*p] = pk2(_a, _c); h[2*p+1] = pk2(_d, _b);                \
        }
    UNMIX_RELU()

    // layer 1
    {
        const ulonglong2* B = (const ulonglong2*)bp1;
        #pragma unroll
        for (int pp = 0; pp < 8; pp++) {
            ulonglong2 b = B[pp];
            am[2*pp] = b.x; am[2*pp+1] = b.y;
            as_[2*pp] = b.x; as_[2*pp+1] = b.y;
        }
        const ulonglong2* W = (const ulonglong2*)wp1;
        #pragma unroll
        for (int j = 0; j < 32; j++) PAIR_J(W, j, h[j])
    }
    UNMIX_RELU()

    // layer 2
    {
        const ulonglong2* B = (const ulonglong2*)bp2;
        #pragma unroll
        for (int pp = 0; pp < 8; pp++) {
            ulonglong2 b = B[pp];
            am[2*pp] = b.x; am[2*pp+1] = b.y;
            as_[2*pp] = b.x; as_[2*pp+1] = b.y;
        }
        const ulonglong2* W = (const ulonglong2*)wp2;
        #pragma unroll
        for (int j = 0; j < 32; j++) PAIR_J(W, j, h[j])
    }
    UNMIX_RELU()
    #undef UNMIX_RELU

    // layer 3: 8 neurons = 4 pairs
    u64 am3[4], as3[4];
    {
        const ulonglong2* B = (const ulonglong2*)bp3;
        #pragma unroll
        for (int pp = 0; pp < 2; pp++) {
            ulonglong2 b = B[pp];
            am3[2*pp] = b.x; am3[2*pp+1] = b.y;
            as3[2*pp] = b.x; as3[2*pp+1] = b.y;
        }
        const ulonglong2* W = (const ulonglong2*)wp3;
        #pragma unroll
        for (int j = 0; j < 32; j++) {
            u64 xj = h[j];
            u64 xs = swp2(xj);
            #pragma unroll
            for (int pp = 0; pp < 2; pp++) {
                ulonglong2 w = W[j * 2 + pp];
                am3[2*pp]   = fma2(xj, w.x, am3[2*pp]);
                as3[2*pp]   = fma2(xs, w.x, as3[2*pp]);
                am3[2*pp+1] = fma2(xj, w.y, am3[2*pp+1]);
                as3[2*pp+1] = fma2(xs, w.y, as3[2*pp+1]);
            }
        }
    }
    #undef PAIR_J
    // un-mix y: yr1[2p]=am.lo, yr2[2p]=as.lo, yr1[2p+1]=as.hi, yr2[2p+1]=am.hi
    float yr1[8], yr2[8];
    #pragma unroll
    for (int p = 0; p < 4; p++) {
        float a, b, c, d;
        upk2(am3[p], a, b); upk2(as3[p], c, d);
        yr1[2*p] = a; yr2[2*p] = c; yr1[2*p+1] = d; yr2[2*p+1] = b;
    }
    // residual add + store both rows
    {
        float4 m0 = *(const float4*)&mtr[base1], m1 = *(const float4*)&mtr[base1 + 4];
        float4 o0, o1;
        o0.x = m0.x + yr1[0]; o0.y = m0.y + yr1[1]; o0.z = m0.z + yr1[2]; o0.w = m0.w + yr1[3];
        o1.x = m1.x + yr1[4]; o1.y = m1.y + yr1[5]; o1.z = m1.z + yr1[6]; o1.w = m1.w + yr1[7];
        *(float4*)&out[base1] = o0; *(float4*)&out[base1 + 4] = o1;
        m0 = *(const float4*)&mtr[base2]; m1 = *(const float4*)&mtr[base2 + 4];
        o0.x = m0.x + yr2[0]; o0.y = m0.y + yr2[1]; o0.z = m0.z + yr2[2]; o0.w = m0.w + yr2[3];
        o1.x = m1.x + yr2[4]; o1.y = m1.y + yr2[5]; o1.z = m1.z + yr2[6]; o1.w = m1.w + yr2[7];
        *(float4*)&out[base2] = o0; *(float4*)&out[base2 + 4] = o1;
    }
}

extern "C" void kernel_launch(void* const* d_in, const int* in_sizes, int n_in,
                              void* d_out, int out_size) {
    const float* mtr  = (const float*)d_in[0];
    const float* feat = (const float*)d_in[1];
    const void*  ei   = d_in[2];
    const float* ea   = (const float*)d_in[3];
    const float* ew0 = (const float*)d_in[4],  *eb0 = (const float*)d_in[5];
    const float* ew1 = (const float*)d_in[6],  *eb1 = (const float*)d_in[7];
    const float* ew2 = (const float*)d_in[8],  *eb2 = (const float*)d_in[9];
    const float* ew3 = (const float*)d_in[10], *eb3 = (const float*)d_in[11];
    const float* ow0 = (const float*)d_in[12], *ob0 = (const float*)d_in[13];
    const float* ow1 = (const float*)d_in[14], *ob1 = (const float*)d_in[15];
    const float* ow2 = (const float*)d_in[16], *ob2 = (const float*)d_in[17];
    const float* ow3 = (const float*)d_in[18], *ob3 = (const float*)d_in[19];
    float* out = (float*)d_out;

    k_pre<<<673, 256>>>((const int*)ei, mtr, ei);
    k_edge<<<192, 256>>>(ei, ea, feat, ew0, eb0, ew1, eb1, ew2, eb2, ew3, eb3);
    k_walk<<<N, 256>>>(ei);
    dim3 g(3, N);
    k_out<<<g, 128>>>(mtr, feat, out, ow0, ob0, ow1, ob1, ow2, ob2, ow3, ob3);
}